// round 8
// baseline (speedup 1.0000x reference)
#include <cuda_runtime.h>
#include <cuda_bf16.h>
#include <math.h>
#include <stdint.h>

// B=8, N=64, D=64, E=32. GEMM view: (32768 x 32) @ (32 x 4096), fused
// relu/mask/reduce epilogue + GRU tail. mma.sync m16n8k16 bf16 (HMMA),
// 3-term hi/lo split (fp32-level accuracy). Fragment-major operands:
// W fragments precomputed to global; A & wt fragments staged per-CTA in smem.

typedef unsigned int u32;

// W fragment buffer: [ig(64)][nt(8)][term(2)][lane(32)] uint4
__device__ uint4 g_Wfrag4[32768];   // 512 KB

static __device__ __forceinline__ void split2(float v0, float v1, u32& hi, u32& lo) {
    __nv_bfloat16 h0 = __float2bfloat16(v0);
    __nv_bfloat16 h1 = __float2bfloat16(v1);
    __nv_bfloat16 l0 = __float2bfloat16(v0 - __bfloat162float(h0));
    __nv_bfloat16 l1 = __float2bfloat16(v1 - __bfloat162float(h1));
    hi = ((u32)__bfloat16_as_ushort(h1) << 16) | (u32)__bfloat16_as_ushort(h0);
    lo = ((u32)__bfloat16_as_ushort(l1) << 16) | (u32)__bfloat16_as_ushort(l0);
}

#define MMA16816(c0,c1,c2,c3,a0,a1,a2,a3,b0,b1) \
    asm volatile("mma.sync.aligned.m16n8k16.row.col.f32.bf16.bf16.f32 " \
        "{%0,%1,%2,%3},{%4,%5,%6,%7},{%8,%9},{%0,%1,%2,%3};" \
        : "+f"(c0),"+f"(c1),"+f"(c2),"+f"(c3) \
        : "r"(a0),"r"(a1),"r"(a2),"r"(a3),"r"(b0),"r"(b1))

// ---------------- converter: W_e -> bf16 hi/lo fragments ----------------
__global__ void conv_w_kernel(const float* __restrict__ W_e) {
    // blockIdx.x = k-pair qg (0..15); blockIdx.y = col quarter
    int qg = blockIdx.x;
    int kt = qg >> 3, h = (qg >> 2) & 1, q = qg & 3;
    int k0 = qg * 2;
    u32* W = (u32*)g_Wfrag4;
    int col = blockIdx.y * 1024 + threadIdx.x;
    #pragma unroll
    for (int u = 0; u < 4; u++, col += 256) {
        float w0 = W_e[(size_t)k0 * 4096 + col];
        float w1 = W_e[(size_t)(k0 + 1) * 4096 + col];
        u32 hi, lo; split2(w0, w1, hi, lo);
        int ig = col >> 6, nt = (col >> 3) & 7, n = col & 7;
        int base = ((((ig * 8 + nt) * 2 + 0) * 8 + n) * 4 + q) * 4 + kt * 2 + h;
        W[base]       = hi;   // term 0 (hi); term stride = 32*4 u32
        W[base + 128] = lo;   // term 1 (lo)
    }
}

// ---------------- main kernel ----------------
// dynamic smem layout (bytes)
#define OFF_AF    0        // A frags: [mt(8)][kt(2)][term(2)][lane(32)] uint4 = 16KB
#define OFF_WF    16384    // wt frags: [mt(8)][nt(8)][lane(32)] float4 = 32KB
#define OFF_AGGS  49152    // 128 f
#define OFF_XROW  49664    // 128 f
#define OFF_XK1   50176    // 192 f
#define OFF_H1    50944    // 64 f
#define OFF_XK2   51200    // 192 f
#define OFF_HK2   51968    // 192 f
#define SMEM_SZ   52736

__global__ __launch_bounds__(256, 2) void mp_mma_kernel(
    const float* __restrict__ nodes,   // (8,64,64)
    const float* __restrict__ edges,   // (8,4096,32)
    const float* __restrict__ mask,    // (8,4096,1)
    const float* __restrict__ b_e,     // (4096,)
    const float* __restrict__ Kmat,    // (64,192)
    const float* __restrict__ Rmat,    // (64,192)
    const float* __restrict__ gbias,   // (2,192)
    float* __restrict__ out)           // (8,64,64)
{
    extern __shared__ char sm[];
    u32*    AF   = (u32*)(sm + OFF_AF);
    uint4*  AF4  = (uint4*)(sm + OFF_AF);
    float4* WF4  = (float4*)(sm + OFF_WF);
    float*  aggs = (float*)(sm + OFF_AGGS);
    float*  xrow = (float*)(sm + OFF_XROW);
    float*  xk1  = (float*)(sm + OFF_XK1);
    float*  h1   = (float*)(sm + OFF_H1);
    float*  xk2  = (float*)(sm + OFF_XK2);
    float*  hk2  = (float*)(sm + OFF_HK2);

    const int t    = threadIdx.x;
    const int lane = t & 31;
    const int wid  = t >> 5;
    const int b    = blockIdx.x >> 5;
    const int pair = blockIdx.x & 31;

    if (t < 128) aggs[t] = 0.0f;
    if (t < 128)
        xrow[t] = nodes[((size_t)b * 64 + pair * 2 + (t >> 6)) * 64 + (t & 63)];

    // ---- A conversion: edges rows -> fragment-major hi/lo in smem ----
    {
        int m = t >> 1, half = t & 1;
        int mt = m >> 4, r16 = m & 15, rr = r16 & 7;
        const float* ar = edges + ((size_t)(b * 4096 + pair * 128 + m)) * 32 + half * 16;
        float v[16];
        #pragma unroll
        for (int i = 0; i < 16; i += 4) {
            float4 x = *(const float4*)(ar + i);
            v[i] = x.x; v[i + 1] = x.y; v[i + 2] = x.z; v[i + 3] = x.w;
        }
        #pragma unroll
        for (int i = 0; i < 16; i += 2) {
            int qg = half * 8 + (i >> 1);          // global k-pair 0..15
            int kt = qg >> 3, ql = qg & 7;
            int q = ql & 3, h = ql >> 2;
            int reg = (r16 >> 3) + 2 * h;
            int ln  = rr * 4 + q;
            u32 hi, lo; split2(v[i], v[i + 1], hi, lo);
            AF[(((mt * 2 + kt) * 2 + 0) * 32 + ln) * 4 + reg] = hi;
            AF[(((mt * 2 + kt) * 2 + 1) * 32 + ln) * 4 + reg] = lo;
        }
    }
    // ---- wt fragments: mask*nodes in fragment-major float4 ----
    for (int idx = t; idx < 2048; idx += 256) {
        int mt = idx >> 8, nt = (idx >> 5) & 7, ln = idx & 31;
        int rr = ln >> 2, q = ln & 3;
        int mrow = mt * 16 + rr;
        int c = nt * 8 + 2 * q;
        int il = mrow >> 6;
        int jn1 = mrow & 63, jn2 = (mrow + 8) & 63;
        float m1 = mask[(size_t)b * 4096 + (pair * 2 + il) * 64 + jn1];
        float m2 = mask[(size_t)b * 4096 + (pair * 2 + il) * 64 + jn2];
        float2 n1 = *(const float2*)(nodes + ((size_t)b * 64 + jn1) * 64 + c);
        float2 n2 = *(const float2*)(nodes + ((size_t)b * 64 + jn2) * 64 + c);
        float4 w; w.x = n1.x * m1; w.y = n1.y * m1; w.z = n2.x * m2; w.w = n2.y * m2;
        WF4[idx] = w;
    }
    __syncthreads();

    const int q = lane & 3;

    for (int igl = 0; igl < 8; igl++) {
        int ig = wid * 8 + igl;

        // B fragments: held across all m-tiles (hi term + lo term)
        uint4 Bf[8][2];
        #pragma unroll
        for (int nt = 0; nt < 8; nt++) {
            Bf[nt][0] = g_Wfrag4[((ig * 8 + nt) * 2 + 0) * 32 + lane];
            Bf[nt][1] = g_Wfrag4[((ig * 8 + nt) * 2 + 1) * 32 + lane];
        }

        float s0 = 0.0f, s1 = 0.0f;

        #pragma unroll
        for (int mt = 0; mt < 8; mt++) {
            uint4 Ah0 = AF4[((mt * 2 + 0) * 2 + 0) * 32 + lane];
            uint4 Al0 = AF4[((mt * 2 + 0) * 2 + 1) * 32 + lane];
            uint4 Ah1 = AF4[((mt * 2 + 1) * 2 + 0) * 32 + lane];
            uint4 Al1 = AF4[((mt * 2 + 1) * 2 + 1) * 32 + lane];

            float sm_ = 0.0f;
            #pragma unroll
            for (int nt = 0; nt < 8; nt++) {
                float2 bb = __ldg((const float2*)(b_e + ig * 64 + nt * 8 + 2 * q));
                // 3 independent 2-MMA chains
                float a0 = bb.x, a1 = bb.y, a2 = bb.x, a3 = bb.y;   // hi*hi (+bias)
                float e0 = 0, e1 = 0, e2 = 0, e3 = 0;               // lo*hi
                float d0 = 0, d1 = 0, d2 = 0, d3 = 0;               // hi*lo
                MMA16816(a0,a1,a2,a3, Ah0.x,Ah0.y,Ah0.z,Ah0.w, Bf[nt][0].x, Bf[nt][0].y);
                MMA16816(e0,e1,e2,e3, Al0.x,Al0.y,Al0.z,Al0.w, Bf[nt][0].x, Bf[nt][0].y);
                MMA16816(d0,d1,d2,d3, Ah0.x,Ah0.y,Ah0.z,Ah0.w, Bf[nt][1].x, Bf[nt][1].y);
                MMA16816(a0,a1,a2,a3, Ah1.x,Ah1.y,Ah1.z,Ah1.w, Bf[nt][0].z, Bf[nt][0].w);
                MMA16816(e0,e1,e2,e3, Al1.x,Al1.y,Al1.z,Al1.w, Bf[nt][0].z, Bf[nt][0].w);
                MMA16816(d0,d1,d2,d3, Ah1.x,Ah1.y,Ah1.z,Ah1.w, Bf[nt][1].z, Bf[nt][1].w);

                float4 w = WF4[(mt * 8 + nt) * 32 + lane];
                sm_ = fmaf(fmaxf(a0 + e0 + d0, 0.0f), w.x, sm_);
                sm_ = fmaf(fmaxf(a1 + e1 + d1, 0.0f), w.y, sm_);
                sm_ = fmaf(fmaxf(a2 + e2 + d2, 0.0f), w.z, sm_);
                sm_ = fmaf(fmaxf(a3 + e3 + d3, 0.0f), w.w, sm_);
            }
            if (mt < 4) s0 += sm_; else s1 += sm_;
        }
        // reduce both partial sums across warp, one atomic each
        #pragma unroll
        for (int off = 16; off; off >>= 1) {
            s0 += __shfl_down_sync(0xffffffffu, s0, off);
            s1 += __shfl_down_sync(0xffffffffu, s1, off);
        }
        if (lane == 0) {
            atomicAdd(&aggs[ig], s0);
            atomicAdd(&aggs[64 + ig], s1);
        }
    }
    __syncthreads();

    // ---- GRU tail: 2 inodes ----
    for (int il2 = 0; il2 < 2; il2++) {
        __syncthreads();
        if (t < 192) {
            float s = gbias[t];
            #pragma unroll 8
            for (int k = 0; k < 64; k++)
                s = fmaf(xrow[il2 * 64 + k], Kmat[k * 192 + t], s);
            xk1[t] = s;
        }
        __syncthreads();
        if (t < 64) {
            float z  = 1.0f / (1.0f + expf(-(xk1[t] + gbias[192 + t])));
            float r  = 1.0f / (1.0f + expf(-(xk1[64 + t] + gbias[256 + t])));
            float hh = tanhf(xk1[128 + t] + r * gbias[320 + t]);
            h1[t] = (1.0f - z) * hh;   // h was 0
        }
        __syncthreads();
        if (t < 192) {
            float s1g = gbias[t], s2g = gbias[192 + t];
            #pragma unroll 8
            for (int k = 0; k < 64; k++) {
                s1g = fmaf(aggs[il2 * 64 + k], Kmat[k * 192 + t], s1g);
                s2g = fmaf(h1[k],              Rmat[k * 192 + t], s2g);
            }
            xk2[t] = s1g; hk2[t] = s2g;
        }
        __syncthreads();
        if (t < 64) {
            float z  = 1.0f / (1.0f + expf(-(xk2[t] + hk2[t])));
            float r  = 1.0f / (1.0f + expf(-(xk2[64 + t] + hk2[64 + t])));
            float hh = tanhf(xk2[128 + t] + r * hk2[128 + t]);
            out[((size_t)(b * 64 + pair * 2 + il2)) * 64 + t] =
                z * h1[t] + (1.0f - z) * hh;
        }
    }
}

extern "C" void kernel_launch(void* const* d_in, const int* in_sizes, int n_in,
                              void* d_out, int out_size) {
    const float* nodes = (const float*)d_in[0];
    const float* edges = (const float*)d_in[1];
    const float* mask  = (const float*)d_in[2];
    const float* W_e   = (const float*)d_in[3];
    const float* b_e   = (const float*)d_in[4];
    const float* gk    = (const float*)d_in[5];
    const float* gr    = (const float*)d_in[6];
    const float* gb    = (const float*)d_in[7];
    float* out = (float*)d_out;

    conv_w_kernel<<<dim3(16, 4), 256>>>(W_e);

    cudaFuncSetAttribute(mp_mma_kernel,
                         cudaFuncAttributeMaxDynamicSharedMemorySize, SMEM_SZ);
    mp_mma_kernel<<<256, 256, SMEM_SZ>>>(nodes, edges, mask, b_e,
                                         gk, gr, gb, out);
}